// round 1
// baseline (speedup 1.0000x reference)
#include <cuda_runtime.h>
#include <math.h>

#define NB 32768
#define HID 64

// scratch: [0..3]*NB = v00,v01,fV,V ; [4..7]*NB = h00,h01,fH,H
__device__ float g_scr[8 * NB];

// ---------------------------------------------------------------------------
// Lyapunov kernel: warp handles 4 batch elements. Computes
//   v0 = grad_V @ G0 (2), fV = -sum(grad_V * x), V = 0.5*||t2||^2
// ---------------------------------------------------------------------------
__global__ void __launch_bounds__(256) lyap_kernel(
    const float* __restrict__ x, const float* __restrict__ W1,
    const float* __restrict__ b1, const float* __restrict__ W2,
    const float* __restrict__ b2, const float* __restrict__ G0)
{
    __shared__ float4 sW2[32 * 33];   // [k2][j] = (W[2j][2k2],W[2j+1][2k2],W[2j][2k2+1],W[2j+1][2k2+1])
    __shared__ float2 sW1[8 * 33];    // [n][j]  = (W1[2j][n], W1[2j+1][n])
    __shared__ float2 sb1[32], sb2[32];
    __shared__ float4 sW1g[32];       // [L] = (g0(2L),g1(2L),g0(2L+1),g1(2L+1))
    __shared__ float  sbuf[8][4][64];
    __shared__ float  sx[8][4][8];

    const int tid = threadIdx.x;
    const int wid = tid >> 5, lane = tid & 31;

    for (int idx = tid; idx < 32 * 32; idx += 256) {
        int k2 = idx >> 5, j = idx & 31;
        sW2[k2 * 33 + j] = make_float4(
            W2[(2 * j) * HID + 2 * k2],
            W2[(2 * j + 1) * HID + 2 * k2],
            W2[(2 * j) * HID + 2 * k2 + 1],
            W2[(2 * j + 1) * HID + 2 * k2 + 1]);
    }
    for (int idx = tid; idx < 8 * 32; idx += 256) {
        int n = idx >> 5, j = idx & 31;
        sW1[n * 33 + j] = make_float2(W1[(2 * j) * 8 + n], W1[(2 * j + 1) * 8 + n]);
    }
    if (tid < 32) {
        sb1[tid] = make_float2(b1[2 * tid], b1[2 * tid + 1]);
        sb2[tid] = make_float2(b2[2 * tid], b2[2 * tid + 1]);
        float a0 = 0.f, a1 = 0.f, c0 = 0.f, c1 = 0.f;
        for (int n = 0; n < 8; n++) {
            a0 += W1[(2 * tid) * 8 + n] * G0[n * 2 + 0];
            a1 += W1[(2 * tid) * 8 + n] * G0[n * 2 + 1];
            c0 += W1[(2 * tid + 1) * 8 + n] * G0[n * 2 + 0];
            c1 += W1[(2 * tid + 1) * 8 + n] * G0[n * 2 + 1];
        }
        sW1g[tid] = make_float4(a0, a1, c0, c1);
    }
    __syncthreads();

    const int e0 = (blockIdx.x * 8 + wid) * 4;
    sx[wid][lane >> 3][lane & 7] = x[e0 * 8 + lane];
    __syncwarp();

    // ---- layer 1 (8 -> 64), keep pre-bias z1n for fV ----
    float z1n[4][2];
    #pragma unroll
    for (int e = 0; e < 4; e++) { z1n[e][0] = 0.f; z1n[e][1] = 0.f; }
    #pragma unroll
    for (int n = 0; n < 8; n++) {
        float2 w = sW1[n * 33 + lane];
        #pragma unroll
        for (int e = 0; e < 4; e++) {
            float xv = sx[wid][e][n];
            z1n[e][0] = fmaf(w.x, xv, z1n[e][0]);
            z1n[e][1] = fmaf(w.y, xv, z1n[e][1]);
        }
    }
    float2 bb1 = sb1[lane];
    float t1[4][2];
    #pragma unroll
    for (int e = 0; e < 4; e++) {
        t1[e][0] = tanhf(z1n[e][0] + bb1.x);
        t1[e][1] = tanhf(z1n[e][1] + bb1.y);
        ((float2*)sbuf[wid][e])[lane] = make_float2(t1[e][0], t1[e][1]);
    }
    __syncwarp();

    // ---- layer 2 (64 -> 64) ----
    float acc[4][2];
    #pragma unroll
    for (int e = 0; e < 4; e++) { acc[e][0] = 0.f; acc[e][1] = 0.f; }
    #pragma unroll
    for (int k2 = 0; k2 < 32; k2++) {
        float4 w = sW2[k2 * 33 + lane];
        #pragma unroll
        for (int e = 0; e < 4; e++) {
            float2 tv = ((const float2*)sbuf[wid][e])[k2];
            acc[e][0] = fmaf(w.x, tv.x, acc[e][0]);
            acc[e][1] = fmaf(w.y, tv.x, acc[e][1]);
            acc[e][0] = fmaf(w.z, tv.y, acc[e][0]);
            acc[e][1] = fmaf(w.w, tv.y, acc[e][1]);
        }
    }
    float2 bb2 = sb2[lane];
    float Vp[4], aout[4][2];
    #pragma unroll
    for (int e = 0; e < 4; e++) {
        float u0 = tanhf(acc[e][0] + bb2.x);
        float u1 = tanhf(acc[e][1] + bb2.y);
        Vp[e] = 0.5f * (u0 * u0 + u1 * u1);
        aout[e][0] = u0 * (1.f - u0 * u0);
        aout[e][1] = u1 * (1.f - u1 * u1);
    }
    __syncwarp();
    #pragma unroll
    for (int e = 0; e < 4; e++)
        ((float2*)sbuf[wid][e])[lane] = make_float2(aout[e][0], aout[e][1]);
    __syncwarp();

    // ---- backward through W2 (lane owns k = 2*lane, 2*lane+1) ----
    float cacc[4][2];
    #pragma unroll
    for (int e = 0; e < 4; e++) { cacc[e][0] = 0.f; cacc[e][1] = 0.f; }
    #pragma unroll
    for (int h2 = 0; h2 < 32; h2++) {
        float4 w = sW2[lane * 33 + h2];
        #pragma unroll
        for (int e = 0; e < 4; e++) {
            float2 av = ((const float2*)sbuf[wid][e])[h2];
            cacc[e][0] = fmaf(w.x, av.x, cacc[e][0]);
            cacc[e][0] = fmaf(w.y, av.y, cacc[e][0]);
            cacc[e][1] = fmaf(w.z, av.x, cacc[e][1]);
            cacc[e][1] = fmaf(w.w, av.y, cacc[e][1]);
        }
    }

    float4 g = sW1g[lane];
    float v0p[4], v1p[4], fVp[4];
    #pragma unroll
    for (int e = 0; e < 4; e++) {
        float c0 = cacc[e][0] * (1.f - t1[e][0] * t1[e][0]);
        float c1 = cacc[e][1] * (1.f - t1[e][1] * t1[e][1]);
        fVp[e] = -(c0 * z1n[e][0] + c1 * z1n[e][1]);
        v0p[e] = c0 * g.x + c1 * g.z;
        v1p[e] = c0 * g.y + c1 * g.w;
    }
    #pragma unroll
    for (int off = 16; off; off >>= 1) {
        #pragma unroll
        for (int e = 0; e < 4; e++) {
            v0p[e] += __shfl_xor_sync(0xffffffffu, v0p[e], off);
            v1p[e] += __shfl_xor_sync(0xffffffffu, v1p[e], off);
            fVp[e] += __shfl_xor_sync(0xffffffffu, fVp[e], off);
            Vp[e]  += __shfl_xor_sync(0xffffffffu, Vp[e],  off);
        }
    }
    if (lane < 4) {
        int i = e0 + lane;
        g_scr[0 * NB + i] = v0p[lane];
        g_scr[1 * NB + i] = v1p[lane];
        g_scr[2 * NB + i] = fVp[lane];
        g_scr[3 * NB + i] = Vp[lane];
    }
}

// ---------------------------------------------------------------------------
// Barrier kernel: 3 hidden layers + scalar head; emits h0 (2), fH, H
// ---------------------------------------------------------------------------
__global__ void __launch_bounds__(256) barrier_kernel(
    const float* __restrict__ x, const float* __restrict__ W1,
    const float* __restrict__ b1, const float* __restrict__ W2,
    const float* __restrict__ b2, const float* __restrict__ W3,
    const float* __restrict__ b3, const float* __restrict__ W4,
    const float* __restrict__ b4, const float* __restrict__ G0)
{
    __shared__ float4 sW2[32 * 33];
    __shared__ float4 sW3[32 * 33];
    __shared__ float2 sW1[8 * 33];
    __shared__ float2 sb1[32], sb2[32], sb3[32], sw4[32];
    __shared__ float4 sW1g[32];
    __shared__ float  sbuf[8][4][64];
    __shared__ float  sx[8][4][8];

    const int tid = threadIdx.x;
    const int wid = tid >> 5, lane = tid & 31;

    for (int idx = tid; idx < 32 * 32; idx += 256) {
        int k2 = idx >> 5, j = idx & 31;
        sW2[k2 * 33 + j] = make_float4(
            W2[(2 * j) * HID + 2 * k2], W2[(2 * j + 1) * HID + 2 * k2],
            W2[(2 * j) * HID + 2 * k2 + 1], W2[(2 * j + 1) * HID + 2 * k2 + 1]);
        sW3[k2 * 33 + j] = make_float4(
            W3[(2 * j) * HID + 2 * k2], W3[(2 * j + 1) * HID + 2 * k2],
            W3[(2 * j) * HID + 2 * k2 + 1], W3[(2 * j + 1) * HID + 2 * k2 + 1]);
    }
    for (int idx = tid; idx < 8 * 32; idx += 256) {
        int n = idx >> 5, j = idx & 31;
        sW1[n * 33 + j] = make_float2(W1[(2 * j) * 8 + n], W1[(2 * j + 1) * 8 + n]);
    }
    if (tid < 32) {
        sb1[tid] = make_float2(b1[2 * tid], b1[2 * tid + 1]);
        sb2[tid] = make_float2(b2[2 * tid], b2[2 * tid + 1]);
        sb3[tid] = make_float2(b3[2 * tid], b3[2 * tid + 1]);
        sw4[tid] = make_float2(W4[2 * tid], W4[2 * tid + 1]);
        float a0 = 0.f, a1 = 0.f, c0 = 0.f, c1 = 0.f;
        for (int n = 0; n < 8; n++) {
            a0 += W1[(2 * tid) * 8 + n] * G0[n * 2 + 0];
            a1 += W1[(2 * tid) * 8 + n] * G0[n * 2 + 1];
            c0 += W1[(2 * tid + 1) * 8 + n] * G0[n * 2 + 0];
            c1 += W1[(2 * tid + 1) * 8 + n] * G0[n * 2 + 1];
        }
        sW1g[tid] = make_float4(a0, a1, c0, c1);
    }
    __syncthreads();

    const int e0 = (blockIdx.x * 8 + wid) * 4;
    sx[wid][lane >> 3][lane & 7] = x[e0 * 8 + lane];
    __syncwarp();

    // ---- layer 1 ----
    float z1n[4][2];
    #pragma unroll
    for (int e = 0; e < 4; e++) { z1n[e][0] = 0.f; z1n[e][1] = 0.f; }
    #pragma unroll
    for (int n = 0; n < 8; n++) {
        float2 w = sW1[n * 33 + lane];
        #pragma unroll
        for (int e = 0; e < 4; e++) {
            float xv = sx[wid][e][n];
            z1n[e][0] = fmaf(w.x, xv, z1n[e][0]);
            z1n[e][1] = fmaf(w.y, xv, z1n[e][1]);
        }
    }
    float2 bb1 = sb1[lane];
    float t1[4][2];
    #pragma unroll
    for (int e = 0; e < 4; e++) {
        t1[e][0] = tanhf(z1n[e][0] + bb1.x);
        t1[e][1] = tanhf(z1n[e][1] + bb1.y);
        ((float2*)sbuf[wid][e])[lane] = make_float2(t1[e][0], t1[e][1]);
    }
    __syncwarp();

    // ---- layer 2 ----
    float acc[4][2];
    #pragma unroll
    for (int e = 0; e < 4; e++) { acc[e][0] = 0.f; acc[e][1] = 0.f; }
    #pragma unroll
    for (int k2 = 0; k2 < 32; k2++) {
        float4 w = sW2[k2 * 33 + lane];
        #pragma unroll
        for (int e = 0; e < 4; e++) {
            float2 tv = ((const float2*)sbuf[wid][e])[k2];
            acc[e][0] = fmaf(w.x, tv.x, acc[e][0]);
            acc[e][1] = fmaf(w.y, tv.x, acc[e][1]);
            acc[e][0] = fmaf(w.z, tv.y, acc[e][0]);
            acc[e][1] = fmaf(w.w, tv.y, acc[e][1]);
        }
    }
    float2 bb2 = sb2[lane];
    float t2[4][2];
    __syncwarp();
    #pragma unroll
    for (int e = 0; e < 4; e++) {
        t2[e][0] = tanhf(acc[e][0] + bb2.x);
        t2[e][1] = tanhf(acc[e][1] + bb2.y);
        ((float2*)sbuf[wid][e])[lane] = make_float2(t2[e][0], t2[e][1]);
    }
    __syncwarp();

    // ---- layer 3 ----
    #pragma unroll
    for (int e = 0; e < 4; e++) { acc[e][0] = 0.f; acc[e][1] = 0.f; }
    #pragma unroll
    for (int k2 = 0; k2 < 32; k2++) {
        float4 w = sW3[k2 * 33 + lane];
        #pragma unroll
        for (int e = 0; e < 4; e++) {
            float2 tv = ((const float2*)sbuf[wid][e])[k2];
            acc[e][0] = fmaf(w.x, tv.x, acc[e][0]);
            acc[e][1] = fmaf(w.y, tv.x, acc[e][1]);
            acc[e][0] = fmaf(w.z, tv.y, acc[e][0]);
            acc[e][1] = fmaf(w.w, tv.y, acc[e][1]);
        }
    }
    float2 bb3 = sb3[lane];
    float2 w4 = sw4[lane];
    float Hp[4], a3[4][2];
    #pragma unroll
    for (int e = 0; e < 4; e++) {
        float u0 = tanhf(acc[e][0] + bb3.x);
        float u1 = tanhf(acc[e][1] + bb3.y);
        Hp[e] = w4.x * u0 + w4.y * u1;
        a3[e][0] = w4.x * (1.f - u0 * u0);
        a3[e][1] = w4.y * (1.f - u1 * u1);
    }
    __syncwarp();
    #pragma unroll
    for (int e = 0; e < 4; e++)
        ((float2*)sbuf[wid][e])[lane] = make_float2(a3[e][0], a3[e][1]);
    __syncwarp();

    // ---- backward through W3 ----
    float cacc[4][2];
    #pragma unroll
    for (int e = 0; e < 4; e++) { cacc[e][0] = 0.f; cacc[e][1] = 0.f; }
    #pragma unroll
    for (int h2 = 0; h2 < 32; h2++) {
        float4 w = sW3[lane * 33 + h2];
        #pragma unroll
        for (int e = 0; e < 4; e++) {
            float2 av = ((const float2*)sbuf[wid][e])[h2];
            cacc[e][0] = fmaf(w.x, av.x, cacc[e][0]);
            cacc[e][0] = fmaf(w.y, av.y, cacc[e][0]);
            cacc[e][1] = fmaf(w.z, av.x, cacc[e][1]);
            cacc[e][1] = fmaf(w.w, av.y, cacc[e][1]);
        }
    }
    __syncwarp();
    #pragma unroll
    for (int e = 0; e < 4; e++) {
        float a20 = cacc[e][0] * (1.f - t2[e][0] * t2[e][0]);
        float a21 = cacc[e][1] * (1.f - t2[e][1] * t2[e][1]);
        ((float2*)sbuf[wid][e])[lane] = make_float2(a20, a21);
    }
    __syncwarp();

    // ---- backward through W2 ----
    #pragma unroll
    for (int e = 0; e < 4; e++) { cacc[e][0] = 0.f; cacc[e][1] = 0.f; }
    #pragma unroll
    for (int h2 = 0; h2 < 32; h2++) {
        float4 w = sW2[lane * 33 + h2];
        #pragma unroll
        for (int e = 0; e < 4; e++) {
            float2 av = ((const float2*)sbuf[wid][e])[h2];
            cacc[e][0] = fmaf(w.x, av.x, cacc[e][0]);
            cacc[e][0] = fmaf(w.y, av.y, cacc[e][0]);
            cacc[e][1] = fmaf(w.z, av.x, cacc[e][1]);
            cacc[e][1] = fmaf(w.w, av.y, cacc[e][1]);
        }
    }

    float4 g = sW1g[lane];
    float h0p[4], h1p[4], fHp[4];
    #pragma unroll
    for (int e = 0; e < 4; e++) {
        float c0 = cacc[e][0] * (1.f - t1[e][0] * t1[e][0]);
        float c1 = cacc[e][1] * (1.f - t1[e][1] * t1[e][1]);
        fHp[e] = -(c0 * z1n[e][0] + c1 * z1n[e][1]);
        h0p[e] = c0 * g.x + c1 * g.z;
        h1p[e] = c0 * g.y + c1 * g.w;
    }
    #pragma unroll
    for (int off = 16; off; off >>= 1) {
        #pragma unroll
        for (int e = 0; e < 4; e++) {
            h0p[e] += __shfl_xor_sync(0xffffffffu, h0p[e], off);
            h1p[e] += __shfl_xor_sync(0xffffffffu, h1p[e], off);
            fHp[e] += __shfl_xor_sync(0xffffffffu, fHp[e], off);
            Hp[e]  += __shfl_xor_sync(0xffffffffu, Hp[e],  off);
        }
    }
    if (lane < 4) {
        int i = e0 + lane;
        g_scr[4 * NB + i] = h0p[lane];
        g_scr[5 * NB + i] = h1p[lane];
        g_scr[6 * NB + i] = fHp[lane];
        g_scr[7 * NB + i] = Hp[lane] + b4[0];
    }
}

// ---------------------------------------------------------------------------
// ADMM kernel: 1 thread / element, analytic block inverse of M (Schur form)
// ---------------------------------------------------------------------------
__global__ void __launch_bounds__(64) admm_kernel(
    const float* __restrict__ x, const float* __restrict__ K,
    float* __restrict__ out)
{
    __shared__ float sK[16];
    if (threadIdx.x < 16) sK[threadIdx.x] = K[threadIdx.x];
    __syncthreads();

    int i = blockIdx.x * 64 + threadIdx.x;
    if (i >= NB) return;

    float v00 = g_scr[0 * NB + i], v01 = g_scr[1 * NB + i];
    float fV  = g_scr[2 * NB + i], V   = g_scr[3 * NB + i];
    float h00 = g_scr[4 * NB + i], h01 = g_scr[5 * NB + i];
    float fH  = g_scr[6 * NB + i], H   = g_scr[7 * NB + i];

    const float4* xp = (const float4*)(x + (size_t)i * 8);
    float4 xa = xp[0], xb = xp[1];
    float xv[8] = {xa.x, xa.y, xa.z, xa.w, xb.x, xb.y, xb.z, xb.w};
    float un0 = 0.f, un1 = 0.f;
    #pragma unroll
    for (int n = 0; n < 8; n++) {
        un0 = fmaf(xv[n], sK[2 * n + 0], un0);
        un1 = fmaf(xv[n], sK[2 * n + 1], un1);
    }
    un0 = -un0; un1 = -un1;   // u_nom (M_NOM = 1)

    const float r    = 1.0f / 1.2f;
    const float sig  = 1e-6f;
    const float d    = 2.0f + sig;
    const float dinv = 1.0f / d;
    const float cfac = 1.0f + r * r;
    const float cp   = cfac * (d - 1.0f) * dinv;

    // Schur complement S = cp*(h0 h0^T + v0 v0^T) + d*I  (2x2), inverted analytically
    float S00 = cp * (h00 * h00 + v00 * v00) + d;
    float S01 = cp * (h00 * h01 + v00 * v01);
    float S11 = cp * (h01 * h01 + v01 * v01) + d;
    float idet = 1.0f / (S00 * S11 - S01 * S01);
    float is00 = S11 * idet, is01 = -S01 * idet, is11 = S00 * idet;

    float qu0 = -2.f * un0, qu1 = -2.f * un1;
    const float qr = 100.f, qs = 50.f;
    float lo0 = -(fH + H),     lo2 = -(fH * r + H);
    float hi1 = -(fV + V),     hi3 = -(fV * r + V);

    float xu0 = 0.f, xu1 = 0.f, xw0 = 0.f, xw1 = 0.f, xw2 = 0.f, xw3 = 0.f;
    float z0 = 0.f, z1 = 0.f, z2 = 0.f, z3 = 0.f, z4 = 0.f, z5 = 0.f, z6 = 0.f, z7 = 0.f;
    float y0 = 0.f, y1 = 0.f, y2 = 0.f, y3 = 0.f, y4 = 0.f, y5 = 0.f, y6 = 0.f, y7 = 0.f;

    #pragma unroll 4
    for (int it = 0; it < 80; it++) {
        float w0 = z0 - y0, w1 = z1 - y1, w2 = z2 - y2, w3 = z3 - y3;
        float w4 = z4 - y4, w5 = z5 - y5, w6 = z6 - y6, w7 = z7 - y7;
        // rhs = sig*x - q + A^T w
        float tA = w0 + r * w2, tB = w1 + r * w3;
        float rhsu0 = sig * xu0 - qu0 + h00 * tA + v00 * tB;
        float rhsu1 = sig * xu1 - qu1 + h01 * tA + v01 * tB;
        float rw0 = sig * xw0 - qr + (w4 - w1);
        float rw1 = sig * xw1 - qr + (w5 - w3);
        float rw2 = sig * xw2 - qs + (w6 + w0);
        float rw3 = sig * xw3 - qs + (w7 + w2);
        // x-update via block solve
        float e1 = rw0 + r * rw1, e2 = rw2 + r * rw3;
        float gu0 = rhsu0 - (h00 * e2 - v00 * e1) * dinv;
        float gu1 = rhsu1 - (h01 * e2 - v01 * e1) * dinv;
        xu0 = is00 * gu0 + is01 * gu1;
        xu1 = is01 * gu0 + is11 * gu1;
        float hu = h00 * xu0 + h01 * xu1;
        float vu = v00 * xu0 + v01 * xu1;
        xw0 = (rw0 + vu) * dinv;
        xw1 = (rw1 + r * vu) * dinv;
        xw2 = (rw2 - hu) * dinv;
        xw3 = (rw3 - r * hu) * dinv;
        // z-update: zt = A x, zn = clip(zt + y, lo, hi), y = (zt + y) - zn
        float s0 = hu + xw2 + y0;
        float s1 = vu - xw0 + y1;
        float s2 = r * hu + xw3 + y2;
        float s3 = r * vu - xw1 + y3;
        float s4 = xw0 + y4, s5 = xw1 + y5, s6 = xw2 + y6, s7 = xw3 + y7;
        z0 = fmaxf(s0, lo0); z1 = fminf(s1, hi1);
        z2 = fmaxf(s2, lo2); z3 = fminf(s3, hi3);
        z4 = fmaxf(s4, 0.f); z5 = fmaxf(s5, 0.f);
        z6 = fmaxf(s6, 0.f); z7 = fmaxf(s7, 0.f);
        y0 = s0 - z0; y1 = s1 - z1; y2 = s2 - z2; y3 = s3 - z3;
        y4 = s4 - z4; y5 = s5 - z5; y6 = s6 - z6; y7 = s7 - z7;
    }

    // outputs, tuple-flattened: u(2B) | relax(B) | V(B) | Vdot(B) | H(B) | Hdot(B)
    out[2 * i + 0] = xu0;
    out[2 * i + 1] = xu1;
    out[2 * NB + i] = 0.5f * (xw0 + xw1);
    out[3 * NB + i] = V;
    out[4 * NB + i] = (fV + v00 * xu0 + v01 * xu1) * (1.f + r) * 0.5f;
    out[5 * NB + i] = H;
    out[6 * NB + i] = (fH + h00 * xu0 + h01 * xu1) * (1.f + r) * 0.5f;
}

extern "C" void kernel_launch(void* const* d_in, const int* in_sizes, int n_in,
                              void* d_out, int out_size) {
    const float* x   = (const float*)d_in[0];
    const float* VW1 = (const float*)d_in[1];
    const float* Vb1 = (const float*)d_in[2];
    const float* VW2 = (const float*)d_in[3];
    const float* Vb2 = (const float*)d_in[4];
    const float* HW1 = (const float*)d_in[5];
    const float* Hb1 = (const float*)d_in[6];
    const float* HW2 = (const float*)d_in[7];
    const float* Hb2 = (const float*)d_in[8];
    const float* HW3 = (const float*)d_in[9];
    const float* Hb3 = (const float*)d_in[10];
    const float* HW4 = (const float*)d_in[11];
    const float* Hb4 = (const float*)d_in[12];
    const float* G0  = (const float*)d_in[13];
    const float* K   = (const float*)d_in[14];
    float* out = (float*)d_out;

    lyap_kernel<<<NB / 32, 256>>>(x, VW1, Vb1, VW2, Vb2, G0);
    barrier_kernel<<<NB / 32, 256>>>(x, HW1, Hb1, HW2, Hb2, HW3, Hb3, HW4, Hb4, G0);
    admm_kernel<<<NB / 64, 64>>>(x, K, out);
}